// round 12
// baseline (speedup 1.0000x reference)
#include <cuda_runtime.h>
#include <math.h>
#include <stdint.h>

#define NP 128
#define ND 3
#define DIM (NP*ND)
#define FF 32
#define HH 32
#define BB 128
#define NEDGE (NP*(NP-1))   // 16256
#define NNODE (BB*NP)       // 16384
#define SBM 34              // padded Bm row stride (floats)
#define SRD 34              // padded m-spill row stride (floats)

// scratch (static device arrays, no allocation)
__device__ float g_A [NNODE*FF];   // h_i @ W_hi + e_b1
__device__ float g_Bm[NNODE*FF];   // h_j @ W_hj

// ---- weights in constant memory (filled by async D2D copies at launch) ----
__constant__ __align__(16) float c_ew2[FF*HH];   // e_w2
__constant__ __align__(16) float c_cw1[FF*HH];   // c_w1
__constant__ __align__(16) float c_wd [32];      // e_w1 row 64
__constant__ __align__(16) float c_wds[32];      // e_w1 row 65
__constant__ __align__(16) float c_eb2[32];
__constant__ __align__(16) float c_cb1[32];
__constant__ __align__(16) float c_aw [32];
__constant__ __align__(16) float c_cw2[32];
__constant__ __align__(16) float c_ab [4];
__constant__ __align__(16) float c_nw1[2*FF*HH]; // n_w1
__constant__ __align__(16) float c_nw2[HH*FF];   // n_w2
__constant__ __align__(16) float c_nb1[32];
__constant__ __align__(16) float c_nb2[32];

// ---- packed f32x2 helpers (FFMA2 via PTX) ----
#define FMA2(d,a,b,c) asm("fma.rn.f32x2 %0, %1, %2, %3;" : "=l"(d) : "l"(a), "l"(b), "l"(c))
#define ADD2(d,a,b)   asm("add.rn.f32x2 %0, %1, %2;"     : "=l"(d) : "l"(a), "l"(b))
#define MUL2(d,a,b)   asm("mul.rn.f32x2 %0, %1, %2;"     : "=l"(d) : "l"(a), "l"(b))
#define PACK2(d,lo,hi) asm("mov.b64 %0, {%1, %2};" : "=l"(d) : "f"(lo), "f"(hi))
#define UNPK2(lo,hi,s) asm("mov.b64 {%0, %1}, %2;" : "=f"(lo), "=f"(hi) : "l"(s))

typedef unsigned long long u64;

__device__ __forceinline__ float tanhap(float v) {
    float t;
    asm("tanh.approx.f32 %0, %1;" : "=f"(t) : "f"(v));
    return t;
}
// silu(v) = 0.5v * (1 + tanh(v/2))  -> 1 MUFU + 2 fma
__device__ __forceinline__ float silut(float v) {
    float hv = 0.5f * v;
    return fmaf(hv, tanhap(hv), hv);
}
// sigmoid(x) = 0.5 tanh(x/2) + 0.5  -> 1 MUFU + 2 fma
__device__ __forceinline__ float sigt(float v) {
    return fmaf(0.5f, tanhap(0.5f * v), 0.5f);
}
__device__ __forceinline__ float siluf(float v) {   // precise (prenode path unused here)
    return __fdividef(v, 1.0f + __expf(-v));
}

// ---------------------------------------------------------------------------
// Kernel 0: per-node precompute A = h@W_hi + e_b1, Bm = h@W_hj
// ---------------------------------------------------------------------------
__global__ __launch_bounds__(128) void prenode_kernel(
    const float* __restrict__ h, const float* __restrict__ e_w1,
    const float* __restrict__ e_b1)
{
    int node = blockIdx.x * 4 + (threadIdx.x >> 5);
    int f    = threadIdx.x & 31;
    float hv = h[node*FF + f];
    float a  = e_b1[f];
    float bm = 0.0f;
#pragma unroll
    for (int k = 0; k < FF; k++) {
        float hk = __shfl_sync(0xffffffffu, hv, k);
        a  += hk * e_w1[k*HH + f];
        bm += hk * e_w1[(FF + k)*HH + f];
    }
    g_A [node*FF + f] = a;
    g_Bm[node*FF + f] = bm;
}

// ---------------------------------------------------------------------------
// Kernel 1: fused edge + node kernel. Block = (b, 4 i's = 2 pairs).
// Weights from __constant__ (uniform port); smem only for per-thread data.
// ---------------------------------------------------------------------------
__global__ __launch_bounds__(128, 4) void edge_kernel(
    const float* __restrict__ x,      const float* __restrict__ d_static,
    const float* __restrict__ h,
    float* __restrict__ x_out,        float* __restrict__ h_out)
{
    __shared__ __align__(16) float s_ai[4*32];      // A_i rows for the 4 i's
    __shared__ __align__(16) float s_bm[NP*SBM];    // staged Bm rows (batch b)
    __shared__ __align__(16) float s_red[NP*SRD];   // m spill / reduce buffer
    __shared__ float s_part[2][4][32];
    __shared__ float s_xp[2][4][3];
    __shared__ float s_xi[4][3];

    const int t = threadIdx.x;
    const int b    = blockIdx.x >> 5;
    const int iblk = (blockIdx.x & 31) * 4;
    const int j = t;
    const int lane = t & 31;
    const int warp = t >> 5;

    {   // coalesced stage of Bm for batch b (128 rows x 32 floats), stride SBM
        const float4* src = (const float4*)(g_Bm + b*NP*FF);
#pragma unroll
        for (int q = 0; q < 8; q++) {
            int idx = q*128 + t;
            int row = idx >> 3;
            int col = (idx & 7) * 4;
            float4 v = src[idx];
            s_bm[row*SBM + col + 0] = v.x;
            s_bm[row*SBM + col + 1] = v.y;
            s_bm[row*SBM + col + 2] = v.z;
            s_bm[row*SBM + col + 3] = v.w;
        }
    }
    s_ai[t] = g_A[(b*NP + iblk + (t >> 5))*FF + (t & 31)];
    if (t < 12) s_xi[t/3][t%3] = x[b*DIM + (iblk + t/3)*ND + (t%3)];
    __syncthreads();

    // invariant per-thread loads
    const float xj0 = x[b*DIM + j*ND + 0];
    const float xj1 = x[b*DIM + j*ND + 1];
    const float xj2 = x[b*DIM + j*ND + 2];

    for (int p = 0; p < 2; p++) {
        const int i0 = iblk + 2*p, i1 = i0 + 1;

        // ---- geometry for both edges ----
        float rxa = s_xi[2*p][0]-xj0, rya = s_xi[2*p][1]-xj1, rza = s_xi[2*p][2]-xj2;
        float rxb = s_xi[2*p+1][0]-xj0, ryb = s_xi[2*p+1][1]-xj1, rzb = s_xi[2*p+1][2]-xj2;
        float d2a = rxa*rxa + rya*rya + rza*rza;
        float d2b = rxb*rxb + ryb*ryb + rzb*rzb;

        int ea = i0*(NP-1) + (j < i0 ? j : j-1); if (j == i0) ea = 0;
        int eb = i1*(NP-1) + (j < i1 ? j : j-1); if (j == i1) eb = 0;
        float dsa = d_static[b*NEDGE + ea];
        float dsb = d_static[b*NEDGE + eb];
        float ds2a = dsa*dsa, ds2b = dsb*dsb;

        u64 d2ap, ds2ap, d2bp, ds2bp;
        PACK2(d2ap, d2a, d2a);  PACK2(ds2ap, ds2a, ds2a);
        PACK2(d2bp, d2b, d2b);  PACK2(ds2bp, ds2b, ds2b);

        // ---- fused layer1->layer2 for both edges; weights from constant ----
        u64 m2a[16], m2b[16];
#pragma unroll
        for (int q = 0; q < 16; q++) {
            u64 bz = *(const u64*)(c_eb2 + 2*q);
            m2a[q] = bz;  m2b[q] = bz;
        }
        {
            const u64* Ai0p = (const u64*)(s_ai + p*64);
            const u64* Ai1p = (const u64*)(s_ai + p*64 + 32);
#pragma unroll 4
            for (int kp = 0; kp < 16; kp++) {
                u64 bm = *(const u64*)(s_bm + j*SBM + 2*kp);
                u64 wd = *(const u64*)(c_wd  + 2*kp);
                u64 ws = *(const u64*)(c_wds + 2*kp);
                u64 pa, pb;
                ADD2(pa, Ai0p[kp], bm);
                FMA2(pa, d2ap, wd, pa);
                FMA2(pa, ds2ap, ws, pa);
                ADD2(pb, Ai1p[kp], bm);
                FMA2(pb, d2bp, wd, pb);
                FMA2(pb, ds2bp, ws, pb);
                float va0, va1, vb0, vb1;
                UNPK2(va0, va1, pa);
                UNPK2(vb0, vb1, pb);
                va0 = silut(va0); va1 = silut(va1);
                vb0 = silut(vb0); vb1 = silut(vb1);
                u64 s0a, s1a, s0b, s1b;
                PACK2(s0a, va0, va0); PACK2(s1a, va1, va1);
                PACK2(s0b, vb0, vb0); PACK2(s1b, vb1, vb1);
#pragma unroll
                for (int q = 0; q < 8; q++) {
                    ulonglong2 wa = *(const ulonglong2*)(c_ew2 + (2*kp)*HH + 4*q);
                    ulonglong2 wb = *(const ulonglong2*)(c_ew2 + (2*kp+1)*HH + 4*q);
                    FMA2(m2a[2*q],   s0a, wa.x, m2a[2*q]);
                    FMA2(m2a[2*q+1], s0a, wa.y, m2a[2*q+1]);
                    FMA2(m2a[2*q],   s1a, wb.x, m2a[2*q]);
                    FMA2(m2a[2*q+1], s1a, wb.y, m2a[2*q+1]);
                    FMA2(m2b[2*q],   s0b, wa.x, m2b[2*q]);
                    FMA2(m2b[2*q+1], s0b, wa.y, m2b[2*q+1]);
                    FMA2(m2b[2*q],   s1b, wb.x, m2b[2*q]);
                    FMA2(m2b[2*q+1], s1b, wb.y, m2b[2*q+1]);
                }
            }
        }

        // ---- silu on m (kept packed) ----
#pragma unroll
        for (int q = 0; q < 16; q++) {
            float v0, v1;
            UNPK2(v0, v1, m2a[q]); v0 = silut(v0); v1 = silut(v1); PACK2(m2a[q], v0, v1);
            UNPK2(v0, v1, m2b[q]); v0 = silut(v0); v1 = silut(v1); PACK2(m2b[q], v0, v1);
        }

        // ---- attention gates (packed dot) + validity mask folded in ----
        {
            u64 ata = 0ull, atb = 0ull;
#pragma unroll
            for (int q = 0; q < 16; q++) {
                u64 w = *(const u64*)(c_aw + 2*q);
                FMA2(ata, m2a[q], w, ata);
                FMA2(atb, m2b[q], w, atb);
            }
            float a0, a1;
            UNPK2(a0, a1, ata);
            float atta = sigt(a0 + a1 + c_ab[0]);
            UNPK2(a0, a1, atb);
            float attb = sigt(a0 + a1 + c_ab[0]);
            if (j == i0) atta = 0.0f;
            if (j == i1) attb = 0.0f;
            u64 pa, pb;
            PACK2(pa, atta, atta);
            PACK2(pb, attb, attb);
#pragma unroll
            for (int q = 0; q < 16; q++) {
                MUL2(m2a[q], m2a[q], pa);
                MUL2(m2b[q], m2b[q], pb);
            }
        }

        // ---- spill masked m (edge a) to smem ----
#pragma unroll
        for (int q = 0; q < 16; q++)
            *(u64*)(s_red + j*SRD + 2*q) = m2a[q];
        __syncthreads();   // sync1

        // ---- reduce-a: thread (f, q4) sums 32 j's of feature f ----
        {
            int f = t & 31, q4 = t >> 5;
            float acc = 0.0f;
            const float* base = s_red + (q4*32)*SRD + f;
#pragma unroll
            for (int n = 0; n < 32; n++) acc += base[n*SRD];
            s_part[0][q4][f] = acc;
        }

        // ---- coord head: interleaved edges, output-halved; weights constant ----
        float acca = 0.0f, accb = 0.0f;
#pragma unroll
        for (int hc = 0; hc < 2; hc++) {
            u64 c2a[8], c2b[8];
#pragma unroll
            for (int q = 0; q < 8; q++) {
                u64 bz = *(const u64*)(c_cb1 + hc*16 + 2*q);
                c2a[q] = bz;  c2b[q] = bz;
            }
#pragma unroll 4
            for (int fp = 0; fp < 16; fp++) {
                u64 mav = *(const u64*)(s_red + j*SRD + 2*fp);
                float ma0, ma1, mb0, mb1;
                UNPK2(ma0, ma1, mav);
                UNPK2(mb0, mb1, m2b[fp]);
                u64 pa0, pa1, pb0, pb1;
                PACK2(pa0, ma0, ma0); PACK2(pa1, ma1, ma1);
                PACK2(pb0, mb0, mb0); PACK2(pb1, mb1, mb1);
#pragma unroll
                for (int q = 0; q < 4; q++) {
                    ulonglong2 wa = *(const ulonglong2*)(c_cw1 + (2*fp)*HH + hc*16 + 4*q);
                    ulonglong2 wb = *(const ulonglong2*)(c_cw1 + (2*fp+1)*HH + hc*16 + 4*q);
                    FMA2(c2a[2*q],   pa0, wa.x, c2a[2*q]);
                    FMA2(c2a[2*q+1], pa0, wa.y, c2a[2*q+1]);
                    FMA2(c2a[2*q],   pa1, wb.x, c2a[2*q]);
                    FMA2(c2a[2*q+1], pa1, wb.y, c2a[2*q+1]);
                    FMA2(c2b[2*q],   pb0, wa.x, c2b[2*q]);
                    FMA2(c2b[2*q+1], pb0, wa.y, c2b[2*q+1]);
                    FMA2(c2b[2*q],   pb1, wb.x, c2b[2*q]);
                    FMA2(c2b[2*q+1], pb1, wb.y, c2b[2*q+1]);
                }
            }
#pragma unroll
            for (int q = 0; q < 8; q++) {
                float c0, c1v;
                UNPK2(c0, c1v, c2a[q]);
                acca += silut(c0)  * c_cw2[hc*16 + 2*q];
                acca += silut(c1v) * c_cw2[hc*16 + 2*q + 1];
                UNPK2(c0, c1v, c2b[q]);
                accb += silut(c0)  * c_cw2[hc*16 + 2*q];
                accb += silut(c1v) * c_cw2[hc*16 + 2*q + 1];
            }
        }
        float transa = tanhf(acca);
        float transb = tanhf(accb);

        float valida = (j == i0) ? 0.0f : 1.0f;
        float validb = (j == i1) ? 0.0f : 1.0f;
        float da = sqrtf(d2a + 1e-6f);
        float db = sqrtf(d2b + 1e-6f);
        float coefa = valida * __fdividef(transa, da + 1.0f);
        float coefb = validb * __fdividef(transb, db + 1.0f);

        __syncthreads();   // sync2: all s_red(a) reads done

        // ---- spill masked m (edge b) and reduce-b ----
#pragma unroll
        for (int q = 0; q < 16; q++)
            *(u64*)(s_red + j*SRD + 2*q) = m2b[q];
        __syncthreads();   // sync3
        {
            int f = t & 31, q4 = t >> 5;
            float acc = 0.0f;
            const float* base = s_red + (q4*32)*SRD + f;
#pragma unroll
            for (int n = 0; n < 32; n++) acc += base[n*SRD];
            s_part[1][q4][f] = acc;
        }

        // ---- coord update reductions (both edges, warp butterfly) ----
        {
            float x0 = rxa*coefa, x1 = rya*coefa, x2 = rza*coefa;
            float y0 = rxb*coefb, y1 = ryb*coefb, y2 = rzb*coefb;
#pragma unroll
            for (int off = 16; off > 0; off >>= 1) {
                x0 += __shfl_xor_sync(0xffffffffu, x0, off);
                x1 += __shfl_xor_sync(0xffffffffu, x1, off);
                x2 += __shfl_xor_sync(0xffffffffu, x2, off);
                y0 += __shfl_xor_sync(0xffffffffu, y0, off);
                y1 += __shfl_xor_sync(0xffffffffu, y1, off);
                y2 += __shfl_xor_sync(0xffffffffu, y2, off);
            }
            if (lane == 0) {
                s_xp[0][warp][0] = x0; s_xp[0][warp][1] = x1; s_xp[0][warp][2] = x2;
                s_xp[1][warp][0] = y0; s_xp[1][warp][1] = y1; s_xp[1][warp][2] = y2;
            }
        }
        __syncthreads();   // sync4

        // ---- tail: warp 0 -> node i0, warp 1 -> node i1 ----
        if (warp < 2) {
            int e = warp;
            int node = b*NP + i0 + e;
            int f = lane;
            if (f < 3) {
                float xs = s_xp[e][0][f] + s_xp[e][1][f] + s_xp[e][2][f] + s_xp[e][3][f];
                x_out[b*DIM + (i0+e)*ND + f] = s_xi[2*p+e][f] + xs * 5.0f;  // COORDS_RANGE
            }
            float mi = s_part[e][0][f] + s_part[e][1][f] + s_part[e][2][f] + s_part[e][3][f];
            float hv = h[node*FF + f];
            float acc = c_nb1[f];
#pragma unroll
            for (int k = 0; k < FF; k++)
                acc += __shfl_sync(0xffffffffu, hv, k) * c_nw1[k*HH + f];
#pragma unroll
            for (int k = 0; k < FF; k++)
                acc += __shfl_sync(0xffffffffu, mi, k) * c_nw1[(FF + k)*HH + f];
            float tt2 = siluf(acc);   // precise silu on node path (cheap, 2 warps)
            float acc2 = c_nb2[f];
#pragma unroll
            for (int k = 0; k < HH; k++)
                acc2 += __shfl_sync(0xffffffffu, tt2, k) * c_nw2[k*FF + f];
            h_out[node*FF + f] = hv + acc2;
        }
    }
}

// ---------------------------------------------------------------------------
extern "C" void kernel_launch(void* const* d_in, const int* in_sizes, int n_in,
                              void* d_out, int out_size)
{
    const float* x        = (const float*)d_in[0];
    const float* h        = (const float*)d_in[1];
    const float* d_static = (const float*)d_in[2];
    const float* e_w1     = (const float*)d_in[3];
    const float* e_b1     = (const float*)d_in[4];
    const float* e_w2     = (const float*)d_in[5];
    const float* e_b2     = (const float*)d_in[6];
    const float* n_w1     = (const float*)d_in[7];
    const float* n_b1     = (const float*)d_in[8];
    const float* n_w2     = (const float*)d_in[9];
    const float* n_b2     = (const float*)d_in[10];
    const float* c_w1     = (const float*)d_in[11];
    const float* c_b1     = (const float*)d_in[12];
    const float* c_w2     = (const float*)d_in[13];
    const float* a_w      = (const float*)d_in[14];
    const float* a_b      = (const float*)d_in[15];

    float* out   = (float*)d_out;
    float* x_out = out;                 // B*DIM floats
    float* h_out = out + BB*DIM;        // B*NP*FF floats

    // stage weights into constant memory (device-to-device, graph-capturable)
    cudaMemcpyToSymbolAsync(c_ew2, e_w2, FF*HH*sizeof(float), 0, cudaMemcpyDeviceToDevice);
    cudaMemcpyToSymbolAsync(c_cw1, c_w1, FF*HH*sizeof(float), 0, cudaMemcpyDeviceToDevice);
    cudaMemcpyToSymbolAsync(c_wd,  e_w1 + (2*FF)*HH,     32*sizeof(float), 0, cudaMemcpyDeviceToDevice);
    cudaMemcpyToSymbolAsync(c_wds, e_w1 + (2*FF + 1)*HH, 32*sizeof(float), 0, cudaMemcpyDeviceToDevice);
    cudaMemcpyToSymbolAsync(c_eb2, e_b2, 32*sizeof(float), 0, cudaMemcpyDeviceToDevice);
    cudaMemcpyToSymbolAsync(c_cb1, c_b1, 32*sizeof(float), 0, cudaMemcpyDeviceToDevice);
    cudaMemcpyToSymbolAsync(c_aw,  a_w,  32*sizeof(float), 0, cudaMemcpyDeviceToDevice);
    cudaMemcpyToSymbolAsync(c_cw2, c_w2, 32*sizeof(float), 0, cudaMemcpyDeviceToDevice);
    cudaMemcpyToSymbolAsync(c_ab,  a_b,  sizeof(float),    0, cudaMemcpyDeviceToDevice);
    cudaMemcpyToSymbolAsync(c_nw1, n_w1, 2*FF*HH*sizeof(float), 0, cudaMemcpyDeviceToDevice);
    cudaMemcpyToSymbolAsync(c_nw2, n_w2, HH*FF*sizeof(float),   0, cudaMemcpyDeviceToDevice);
    cudaMemcpyToSymbolAsync(c_nb1, n_b1, 32*sizeof(float), 0, cudaMemcpyDeviceToDevice);
    cudaMemcpyToSymbolAsync(c_nb2, n_b2, 32*sizeof(float), 0, cudaMemcpyDeviceToDevice);

    prenode_kernel<<<NNODE/4, 128>>>(h, e_w1, e_b1);
    edge_kernel<<<BB*NP/4, 128>>>(x, d_static, h, x_out, h_out);
}

// round 13
// speedup vs baseline: 3.0456x; 3.0456x over previous
#include <cuda_runtime.h>
#include <math.h>

#define NP 128
#define ND 3
#define DIM (NP*ND)
#define FF 32
#define HH 32
#define BB 128
#define NEDGE (NP*(NP-1))   // 16256
#define NNODE (BB*NP)       // 16384
#define SBM 34              // padded Bm row stride (floats)
#define SRD 34              // padded m-spill row stride (floats)

// scratch (static device arrays, no allocation)
__device__ float g_A [NNODE*FF];   // h_i @ W_hi + e_b1
__device__ float g_Bm[NNODE*FF];   // h_j @ W_hj

// ---- packed f32x2 helpers (FFMA2 via PTX) ----
#define FMA2(d,a,b,c) asm("fma.rn.f32x2 %0, %1, %2, %3;" : "=l"(d) : "l"(a), "l"(b), "l"(c))
#define ADD2(d,a,b)   asm("add.rn.f32x2 %0, %1, %2;"     : "=l"(d) : "l"(a), "l"(b))
#define MUL2(d,a,b)   asm("mul.rn.f32x2 %0, %1, %2;"     : "=l"(d) : "l"(a), "l"(b))
#define PACK2(d,lo,hi) asm("mov.b64 %0, {%1, %2};" : "=l"(d) : "f"(lo), "f"(hi))
#define UNPK2(lo,hi,s) asm("mov.b64 {%0, %1}, %2;" : "=f"(lo), "=f"(hi) : "l"(s))

typedef unsigned long long u64;

__device__ __forceinline__ float tanhap(float v) {
    float t;
    asm("tanh.approx.f32 %0, %1;" : "=f"(t) : "f"(v));
    return t;
}
// silu(v) = 0.5v * (1 + tanh(v/2))  -> 1 MUFU + 2 fma   (validated: rel_err ~4e-8)
__device__ __forceinline__ float silut(float v) {
    float hv = 0.5f * v;
    return fmaf(hv, tanhap(hv), hv);
}
// sigmoid(x) = 0.5 tanh(x/2) + 0.5  -> 1 MUFU + 2 fma
__device__ __forceinline__ float sigt(float v) {
    return fmaf(0.5f, tanhap(0.5f * v), 0.5f);
}
__device__ __forceinline__ float siluf(float v) {   // precise (node tail, 2 warps only)
    return __fdividef(v, 1.0f + __expf(-v));
}

// ---------------------------------------------------------------------------
// Kernel 0: per-node precompute A = h@W_hi + e_b1, Bm = h@W_hj
// ---------------------------------------------------------------------------
__global__ __launch_bounds__(128) void prenode_kernel(
    const float* __restrict__ h, const float* __restrict__ e_w1,
    const float* __restrict__ e_b1)
{
    int node = blockIdx.x * 4 + (threadIdx.x >> 5);
    int f    = threadIdx.x & 31;
    float hv = h[node*FF + f];
    float a  = e_b1[f];
    float bm = 0.0f;
#pragma unroll
    for (int k = 0; k < FF; k++) {
        float hk = __shfl_sync(0xffffffffu, hv, k);
        a  += hk * e_w1[k*HH + f];
        bm += hk * e_w1[(FF + k)*HH + f];
    }
    g_A [node*FF + f] = a;
    g_Bm[node*FF + f] = bm;
}

// ---------------------------------------------------------------------------
// Kernel 1: fused edge + node kernel.
// Block = (b, 4 i's = 2 pairs). Thread j handles edges (i0->j),(i1->j) per pair.
// Edge-a's m spilled to smem (frees regs; doubles as the m_i reduce buffer);
// coord head output-halved. Weights stream from smem (broadcast LDS.128).
// Fast tanh-based activations (1 MUFU each).
// ---------------------------------------------------------------------------
__global__ __launch_bounds__(128, 4) void edge_kernel(
    const float* __restrict__ x,      const float* __restrict__ d_static,
    const float* __restrict__ e_w1,   const float* __restrict__ e_w2,
    const float* __restrict__ e_b2,   const float* __restrict__ c_w1,
    const float* __restrict__ c_b1,   const float* __restrict__ c_w2,
    const float* __restrict__ a_w,    const float* __restrict__ a_b,
    const float* __restrict__ h,
    const float* __restrict__ n_w1,   const float* __restrict__ n_b1,
    const float* __restrict__ n_w2,   const float* __restrict__ n_b2,
    float* __restrict__ x_out,        float* __restrict__ h_out)
{
    __shared__ __align__(16) float s_w2[FF*HH];     // e_w2
    __shared__ __align__(16) float s_c1[FF*HH];     // c_w1
    __shared__ __align__(16) float s_misc[10*32];   // wd,wds,eb2,cb1,aw,cw2,Ai0..Ai3
    __shared__ __align__(16) float s_bm[NP*SBM];    // staged Bm rows (batch b)
    __shared__ __align__(16) float s_red[NP*SRD];   // m spill / reduce buffer
    __shared__ float s_part[2][4][32];
    __shared__ float s_xp[2][4][3];
    __shared__ float s_xi[4][3];
    __shared__ float s_ab;

    const int t = threadIdx.x;
    const int b    = blockIdx.x >> 5;
    const int iblk = (blockIdx.x & 31) * 4;
    const int j = t;
    const int lane = t & 31;
    const int warp = t >> 5;

    for (int idx = t; idx < FF*HH; idx += 128) {
        s_w2[idx] = e_w2[idx];
        s_c1[idx] = c_w1[idx];
    }
    {   // coalesced stage of Bm for batch b (128 rows x 32 floats), stride SBM
        const float4* src = (const float4*)(g_Bm + b*NP*FF);
#pragma unroll
        for (int q = 0; q < 8; q++) {
            int idx = q*128 + t;
            int row = idx >> 3;
            int col = (idx & 7) * 4;
            float4 v = src[idx];
            s_bm[row*SBM + col + 0] = v.x;
            s_bm[row*SBM + col + 1] = v.y;
            s_bm[row*SBM + col + 2] = v.z;
            s_bm[row*SBM + col + 3] = v.w;
        }
    }
    if (t < 32) {
        s_misc[t      ] = e_w1[(2*FF    )*HH + t];  // w_d
        s_misc[32 + t ] = e_w1[(2*FF + 1)*HH + t];  // w_ds
        s_misc[64 + t ] = e_b2[t];
        s_misc[96 + t ] = c_b1[t];
        s_misc[128 + t] = a_w[t];
        s_misc[160 + t] = c_w2[t];
    }
    // A_i rows for the 4 i's
    s_misc[192 + t] = g_A[(b*NP + iblk + (t >> 5))*FF + (t & 31)];
    if (t == 0) s_ab = a_b[0];
    if (t < 12) s_xi[t/3][t%3] = x[b*DIM + (iblk + t/3)*ND + (t%3)];
    __syncthreads();

    // invariant per-thread loads
    const float xj0 = x[b*DIM + j*ND + 0];
    const float xj1 = x[b*DIM + j*ND + 1];
    const float xj2 = x[b*DIM + j*ND + 2];

    for (int p = 0; p < 2; p++) {
        const int i0 = iblk + 2*p, i1 = i0 + 1;

        // ---- geometry for both edges ----
        float rxa = s_xi[2*p][0]-xj0, rya = s_xi[2*p][1]-xj1, rza = s_xi[2*p][2]-xj2;
        float rxb = s_xi[2*p+1][0]-xj0, ryb = s_xi[2*p+1][1]-xj1, rzb = s_xi[2*p+1][2]-xj2;
        float d2a = rxa*rxa + rya*rya + rza*rza;
        float d2b = rxb*rxb + ryb*ryb + rzb*rzb;

        int ea = i0*(NP-1) + (j < i0 ? j : j-1); if (j == i0) ea = 0;
        int eb = i1*(NP-1) + (j < i1 ? j : j-1); if (j == i1) eb = 0;
        float dsa = d_static[b*NEDGE + ea];
        float dsb = d_static[b*NEDGE + eb];
        float ds2a = dsa*dsa, ds2b = dsb*dsb;

        u64 d2ap, ds2ap, d2bp, ds2bp;
        PACK2(d2ap, d2a, d2a);  PACK2(ds2ap, ds2a, ds2a);
        PACK2(d2bp, d2b, d2b);  PACK2(ds2bp, ds2b, ds2b);

        // ---- fused layer1->layer2 for both edges, weights loaded once ----
        u64 m2a[16], m2b[16];
        {
            const ulonglong2* bp = (const ulonglong2*)(s_misc + 64);
#pragma unroll
            for (int q = 0; q < 8; q++) {
                ulonglong2 v = bp[q];
                m2a[2*q] = v.x;  m2a[2*q+1] = v.y;
                m2b[2*q] = v.x;  m2b[2*q+1] = v.y;
            }
        }
        {
            const u64* Ai0p = (const u64*)(s_misc + 192 + p*64);
            const u64* Ai1p = (const u64*)(s_misc + 224 + p*64);
            const u64* Wd   = (const u64*)(s_misc + 0);
            const u64* Wds  = (const u64*)(s_misc + 32);
#pragma unroll 4
            for (int kp = 0; kp < 16; kp++) {
                u64 bm = *(const u64*)(s_bm + j*SBM + 2*kp);
                u64 wd = Wd[kp], ws = Wds[kp];
                u64 pa, pb;
                ADD2(pa, Ai0p[kp], bm);
                FMA2(pa, d2ap, wd, pa);
                FMA2(pa, ds2ap, ws, pa);
                ADD2(pb, Ai1p[kp], bm);
                FMA2(pb, d2bp, wd, pb);
                FMA2(pb, ds2bp, ws, pb);
                float va0, va1, vb0, vb1;
                UNPK2(va0, va1, pa);
                UNPK2(vb0, vb1, pb);
                va0 = silut(va0); va1 = silut(va1);
                vb0 = silut(vb0); vb1 = silut(vb1);
                u64 s0a, s1a, s0b, s1b;
                PACK2(s0a, va0, va0); PACK2(s1a, va1, va1);
                PACK2(s0b, vb0, vb0); PACK2(s1b, vb1, vb1);
                const ulonglong2* w0 = (const ulonglong2*)(s_w2 + (2*kp)*HH);
#pragma unroll
                for (int q = 0; q < 8; q++) {
                    ulonglong2 wa = w0[q], wb = w0[q+8];
                    FMA2(m2a[2*q],   s0a, wa.x, m2a[2*q]);
                    FMA2(m2a[2*q+1], s0a, wa.y, m2a[2*q+1]);
                    FMA2(m2a[2*q],   s1a, wb.x, m2a[2*q]);
                    FMA2(m2a[2*q+1], s1a, wb.y, m2a[2*q+1]);
                    FMA2(m2b[2*q],   s0b, wa.x, m2b[2*q]);
                    FMA2(m2b[2*q+1], s0b, wa.y, m2b[2*q+1]);
                    FMA2(m2b[2*q],   s1b, wb.x, m2b[2*q]);
                    FMA2(m2b[2*q+1], s1b, wb.y, m2b[2*q+1]);
                }
            }
        }

        // ---- silu on m (kept packed) ----
#pragma unroll
        for (int q = 0; q < 16; q++) {
            float v0, v1;
            UNPK2(v0, v1, m2a[q]); v0 = silut(v0); v1 = silut(v1); PACK2(m2a[q], v0, v1);
            UNPK2(v0, v1, m2b[q]); v0 = silut(v0); v1 = silut(v1); PACK2(m2b[q], v0, v1);
        }

        // ---- attention gates (packed dot) + validity mask folded in ----
        {
            const u64* awp = (const u64*)(s_misc + 128);
            u64 ata = 0ull, atb = 0ull;
#pragma unroll
            for (int q = 0; q < 16; q++) {
                u64 w = awp[q];
                FMA2(ata, m2a[q], w, ata);
                FMA2(atb, m2b[q], w, atb);
            }
            float a0, a1;
            UNPK2(a0, a1, ata);
            float atta = sigt(a0 + a1 + s_ab);
            UNPK2(a0, a1, atb);
            float attb = sigt(a0 + a1 + s_ab);
            if (j == i0) atta = 0.0f;      // mask diagonal edge a
            if (j == i1) attb = 0.0f;      // mask diagonal edge b
            u64 pa, pb;
            PACK2(pa, atta, atta);
            PACK2(pb, attb, attb);
#pragma unroll
            for (int q = 0; q < 16; q++) {
                MUL2(m2a[q], m2a[q], pa);
                MUL2(m2b[q], m2b[q], pb);
            }
        }

        // ---- spill masked m (edge a) to smem: frees m2a during coord head ----
#pragma unroll
        for (int q = 0; q < 16; q++)
            *(u64*)(s_red + j*SRD + 2*q) = m2a[q];
        __syncthreads();   // sync1: s_red(a) visible

        // ---- reduce-a: thread (f, q4) sums 32 j's of feature f ----
        {
            int f = t & 31, q4 = t >> 5;
            float acc = 0.0f;
            const float* base = s_red + (q4*32)*SRD + f;
#pragma unroll
            for (int n = 0; n < 32; n++) acc += base[n*SRD];
            s_part[0][q4][f] = acc;
        }

        // ---- coord head: interleaved edges, output-halved; edge-a m streamed
        //      from smem, edge-b m from regs ----
        float acca = 0.0f, accb = 0.0f;
#pragma unroll
        for (int hc = 0; hc < 2; hc++) {
            u64 c2a[8], c2b[8];
            const ulonglong2* cb = (const ulonglong2*)(s_misc + 96 + hc*16);
#pragma unroll
            for (int q = 0; q < 4; q++) {
                ulonglong2 v = cb[q];
                c2a[2*q] = v.x;  c2a[2*q+1] = v.y;
                c2b[2*q] = v.x;  c2b[2*q+1] = v.y;
            }
#pragma unroll 4
            for (int fp = 0; fp < 16; fp++) {
                u64 mav = *(const u64*)(s_red + j*SRD + 2*fp);
                float ma0, ma1, mb0, mb1;
                UNPK2(ma0, ma1, mav);
                UNPK2(mb0, mb1, m2b[fp]);
                u64 pa0, pa1, pb0, pb1;
                PACK2(pa0, ma0, ma0); PACK2(pa1, ma1, ma1);
                PACK2(pb0, mb0, mb0); PACK2(pb1, mb1, mb1);
                const ulonglong2* wr0 = (const ulonglong2*)(s_c1 + (2*fp)*HH + hc*16);
                const ulonglong2* wr1 = (const ulonglong2*)(s_c1 + (2*fp+1)*HH + hc*16);
#pragma unroll
                for (int q = 0; q < 4; q++) {
                    ulonglong2 wa = wr0[q], wb = wr1[q];
                    FMA2(c2a[2*q],   pa0, wa.x, c2a[2*q]);
                    FMA2(c2a[2*q+1], pa0, wa.y, c2a[2*q+1]);
                    FMA2(c2a[2*q],   pa1, wb.x, c2a[2*q]);
                    FMA2(c2a[2*q+1], pa1, wb.y, c2a[2*q+1]);
                    FMA2(c2b[2*q],   pb0, wa.x, c2b[2*q]);
                    FMA2(c2b[2*q+1], pb0, wa.y, c2b[2*q+1]);
                    FMA2(c2b[2*q],   pb1, wb.x, c2b[2*q]);
                    FMA2(c2b[2*q+1], pb1, wb.y, c2b[2*q+1]);
                }
            }
#pragma unroll
            for (int q = 0; q < 8; q++) {
                float c0, c1v;
                UNPK2(c0, c1v, c2a[q]);
                acca += silut(c0)  * s_misc[160 + hc*16 + 2*q];
                acca += silut(c1v) * s_misc[160 + hc*16 + 2*q + 1];
                UNPK2(c0, c1v, c2b[q]);
                accb += silut(c0)  * s_misc[160 + hc*16 + 2*q];
                accb += silut(c1v) * s_misc[160 + hc*16 + 2*q + 1];
            }
        }
        float transa = tanhap(acca);
        float transb = tanhap(accb);

        float valida = (j == i0) ? 0.0f : 1.0f;
        float validb = (j == i1) ? 0.0f : 1.0f;
        float da = sqrtf(d2a + 1e-6f);
        float db = sqrtf(d2b + 1e-6f);
        float coefa = valida * __fdividef(transa, da + 1.0f);
        float coefb = validb * __fdividef(transb, db + 1.0f);

        __syncthreads();   // sync2: all s_red(a) reads done

        // ---- spill masked m (edge b) and reduce-b ----
#pragma unroll
        for (int q = 0; q < 16; q++)
            *(u64*)(s_red + j*SRD + 2*q) = m2b[q];
        __syncthreads();   // sync3
        {
            int f = t & 31, q4 = t >> 5;
            float acc = 0.0f;
            const float* base = s_red + (q4*32)*SRD + f;
#pragma unroll
            for (int n = 0; n < 32; n++) acc += base[n*SRD];
            s_part[1][q4][f] = acc;
        }

        // ---- coord update reductions (both edges, warp butterfly) ----
        {
            float x0 = rxa*coefa, x1 = rya*coefa, x2 = rza*coefa;
            float y0 = rxb*coefb, y1 = ryb*coefb, y2 = rzb*coefb;
#pragma unroll
            for (int off = 16; off > 0; off >>= 1) {
                x0 += __shfl_xor_sync(0xffffffffu, x0, off);
                x1 += __shfl_xor_sync(0xffffffffu, x1, off);
                x2 += __shfl_xor_sync(0xffffffffu, x2, off);
                y0 += __shfl_xor_sync(0xffffffffu, y0, off);
                y1 += __shfl_xor_sync(0xffffffffu, y1, off);
                y2 += __shfl_xor_sync(0xffffffffu, y2, off);
            }
            if (lane == 0) {
                s_xp[0][warp][0] = x0; s_xp[0][warp][1] = x1; s_xp[0][warp][2] = x2;
                s_xp[1][warp][0] = y0; s_xp[1][warp][1] = y1; s_xp[1][warp][2] = y2;
            }
        }
        __syncthreads();   // sync4: s_part / s_xp ready

        // ---- tail: warp 0 -> node i0, warp 1 -> node i1 ----
        if (warp < 2) {
            int e = warp;
            int node = b*NP + i0 + e;
            int f = lane;
            if (f < 3) {
                float xs = s_xp[e][0][f] + s_xp[e][1][f] + s_xp[e][2][f] + s_xp[e][3][f];
                x_out[b*DIM + (i0+e)*ND + f] = s_xi[2*p+e][f] + xs * 5.0f;  // COORDS_RANGE
            }
            float mi = s_part[e][0][f] + s_part[e][1][f] + s_part[e][2][f] + s_part[e][3][f];
            float hv = h[node*FF + f];
            float acc = n_b1[f];
#pragma unroll
            for (int k = 0; k < FF; k++)
                acc += __shfl_sync(0xffffffffu, hv, k) * n_w1[k*HH + f];
#pragma unroll
            for (int k = 0; k < FF; k++)
                acc += __shfl_sync(0xffffffffu, mi, k) * n_w1[(FF + k)*HH + f];
            float tt2 = siluf(acc);
            float acc2 = n_b2[f];
#pragma unroll
            for (int k = 0; k < HH; k++)
                acc2 += __shfl_sync(0xffffffffu, tt2, k) * n_w2[k*FF + f];
            h_out[node*FF + f] = hv + acc2;
        }
    }
}

// ---------------------------------------------------------------------------
extern "C" void kernel_launch(void* const* d_in, const int* in_sizes, int n_in,
                              void* d_out, int out_size)
{
    const float* x        = (const float*)d_in[0];
    const float* h        = (const float*)d_in[1];
    const float* d_static = (const float*)d_in[2];
    const float* e_w1     = (const float*)d_in[3];
    const float* e_b1     = (const float*)d_in[4];
    const float* e_w2     = (const float*)d_in[5];
    const float* e_b2     = (const float*)d_in[6];
    const float* n_w1     = (const float*)d_in[7];
    const float* n_b1     = (const float*)d_in[8];
    const float* n_w2     = (const float*)d_in[9];
    const float* n_b2     = (const float*)d_in[10];
    const float* c_w1     = (const float*)d_in[11];
    const float* c_b1     = (const float*)d_in[12];
    const float* c_w2     = (const float*)d_in[13];
    const float* a_w      = (const float*)d_in[14];
    const float* a_b      = (const float*)d_in[15];

    float* out   = (float*)d_out;
    float* x_out = out;                 // B*DIM floats
    float* h_out = out + BB*DIM;        // B*NP*FF floats

    prenode_kernel<<<NNODE/4, 128>>>(h, e_w1, e_b1);
    edge_kernel<<<BB*NP/4, 128>>>(x, d_static, e_w1, e_w2, e_b2,
                                  c_w1, c_b1, c_w2, a_w, a_b,
                                  h, n_w1, n_b1, n_w2, n_b2,
                                  x_out, h_out);
}

// round 14
// speedup vs baseline: 3.4620x; 1.1367x over previous
#include <cuda_runtime.h>
#include <cuda_fp16.h>
#include <math.h>

#define NP 128
#define ND 3
#define DIM (NP*ND)
#define FF 32
#define HH 32
#define BB 128
#define NEDGE (NP*(NP-1))   // 16256
#define NNODE (BB*NP)       // 16384
#define SBM 34              // padded Bm row stride (floats)
#define SRD 34              // padded m-spill row stride (floats)

// scratch (static device arrays, no allocation)
__device__ float g_A [NNODE*FF];   // h_i @ W_hi + e_b1
__device__ float g_Bm[NNODE*FF];   // h_j @ W_hj

// ---- packed f32x2 helpers (FFMA2 via PTX) ----
#define FMA2(d,a,b,c) asm("fma.rn.f32x2 %0, %1, %2, %3;" : "=l"(d) : "l"(a), "l"(b), "l"(c))
#define ADD2(d,a,b)   asm("add.rn.f32x2 %0, %1, %2;"     : "=l"(d) : "l"(a), "l"(b))
#define MUL2(d,a,b)   asm("mul.rn.f32x2 %0, %1, %2;"     : "=l"(d) : "l"(a), "l"(b))
#define PACK2(d,lo,hi) asm("mov.b64 %0, {%1, %2};" : "=l"(d) : "f"(lo), "f"(hi))
#define UNPK2(lo,hi,s) asm("mov.b64 {%0, %1}, %2;" : "=f"(lo), "=f"(hi) : "l"(s))

typedef unsigned long long u64;

__device__ __forceinline__ float tanhap(float v) {
    float t;
    asm("tanh.approx.f32 %0, %1;" : "=f"(t) : "f"(v));
    return t;
}
// silu(v) = 0.5v * (1 + tanh(v/2))  -> 1 MUFU + 2 fma
__device__ __forceinline__ float silut(float v) {
    float hv = 0.5f * v;
    return fmaf(hv, tanhap(hv), hv);
}
// sigmoid(x) = 0.5 tanh(x/2) + 0.5
__device__ __forceinline__ float sigt(float v) {
    return fmaf(0.5f, tanhap(0.5f * v), 0.5f);
}
__device__ __forceinline__ float siluf(float v) {   // precise (node tail only)
    return __fdividef(v, 1.0f + __expf(-v));
}
__device__ __forceinline__ __half2 h2cast(unsigned int u) {
    return *reinterpret_cast<__half2*>(&u);
}

// ---------------------------------------------------------------------------
// Kernel 0: per-node precompute A = h@W_hi + e_b1, Bm = h@W_hj
// ---------------------------------------------------------------------------
__global__ __launch_bounds__(128) void prenode_kernel(
    const float* __restrict__ h, const float* __restrict__ e_w1,
    const float* __restrict__ e_b1)
{
    int node = blockIdx.x * 4 + (threadIdx.x >> 5);
    int f    = threadIdx.x & 31;
    float hv = h[node*FF + f];
    float a  = e_b1[f];
    float bm = 0.0f;
#pragma unroll
    for (int k = 0; k < FF; k++) {
        float hk = __shfl_sync(0xffffffffu, hv, k);
        a  += hk * e_w1[k*HH + f];
        bm += hk * e_w1[(FF + k)*HH + f];
    }
    g_A [node*FF + f] = a;
    g_Bm[node*FF + f] = bm;
}

// ---------------------------------------------------------------------------
// Kernel 1: fused edge + node kernel.
// Block = (b, 4 i's = 2 pairs). Thread j handles edges (i0->j),(i1->j) per pair.
// GEMM weights stored fp16x2 in smem (HALF the broadcast LDS traffic); the two
// 32x32 GEMVs run on HFMA2 with per-feature (even-k, odd-k) fp16 partial
// accumulators, finalized in fp32 (bias add + silu in fp32). All other math fp32.
// ---------------------------------------------------------------------------
__global__ __launch_bounds__(128, 4) void edge_kernel(
    const float* __restrict__ x,      const float* __restrict__ d_static,
    const float* __restrict__ e_w1,   const float* __restrict__ e_w2,
    const float* __restrict__ e_b2,   const float* __restrict__ c_w1,
    const float* __restrict__ c_b1,   const float* __restrict__ c_w2,
    const float* __restrict__ a_w,    const float* __restrict__ a_b,
    const float* __restrict__ h,
    const float* __restrict__ n_w1,   const float* __restrict__ n_b1,
    const float* __restrict__ n_w2,   const float* __restrict__ n_b2,
    float* __restrict__ x_out,        float* __restrict__ h_out)
{
    // weight layout: s_w2h[kp*32 + f] = { W[2kp][f], W[2kp+1][f] }  (kp = k-pair)
    __shared__ __align__(16) __half2 s_w2h[16*32];   // e_w2, fp16 pairs (2KB)
    __shared__ __align__(16) __half2 s_c1h[16*32];   // c_w1, fp16 pairs (2KB)
    __shared__ __align__(16) float s_misc[10*32];    // wd,wds,eb2,cb1,aw,cw2,Ai0..Ai3
    __shared__ __align__(16) float s_bm[NP*SBM];     // staged Bm rows (batch b)
    __shared__ __align__(16) float s_red[NP*SRD];    // m spill / reduce buffer
    __shared__ float s_part[2][4][32];
    __shared__ float s_xp[2][4][3];
    __shared__ float s_xi[4][3];
    __shared__ float s_ab;

    const int t = threadIdx.x;
    const int b    = blockIdx.x >> 5;
    const int iblk = (blockIdx.x & 31) * 4;
    const int j = t;
    const int lane = t & 31;
    const int warp = t >> 5;

    // stage fp16 weight tiles (one-time)
    for (int idx = t; idx < 512; idx += 128) {
        int kp = idx >> 5, f = idx & 31;
        s_w2h[idx] = __floats2half2_rn(e_w2[(2*kp)*HH + f], e_w2[(2*kp+1)*HH + f]);
        s_c1h[idx] = __floats2half2_rn(c_w1[(2*kp)*HH + f], c_w1[(2*kp+1)*HH + f]);
    }
    {   // coalesced stage of Bm for batch b (128 rows x 32 floats), stride SBM
        const float4* src = (const float4*)(g_Bm + b*NP*FF);
#pragma unroll
        for (int q = 0; q < 8; q++) {
            int idx = q*128 + t;
            int row = idx >> 3;
            int col = (idx & 7) * 4;
            float4 v = src[idx];
            s_bm[row*SBM + col + 0] = v.x;
            s_bm[row*SBM + col + 1] = v.y;
            s_bm[row*SBM + col + 2] = v.z;
            s_bm[row*SBM + col + 3] = v.w;
        }
    }
    if (t < 32) {
        s_misc[t      ] = e_w1[(2*FF    )*HH + t];  // w_d
        s_misc[32 + t ] = e_w1[(2*FF + 1)*HH + t];  // w_ds
        s_misc[64 + t ] = e_b2[t];
        s_misc[96 + t ] = c_b1[t];
        s_misc[128 + t] = a_w[t];
        s_misc[160 + t] = c_w2[t];
    }
    // A_i rows for the 4 i's
    s_misc[192 + t] = g_A[(b*NP + iblk + (t >> 5))*FF + (t & 31)];
    if (t == 0) s_ab = a_b[0];
    if (t < 12) s_xi[t/3][t%3] = x[b*DIM + (iblk + t/3)*ND + (t%3)];
    __syncthreads();

    // invariant per-thread loads
    const float xj0 = x[b*DIM + j*ND + 0];
    const float xj1 = x[b*DIM + j*ND + 1];
    const float xj2 = x[b*DIM + j*ND + 2];

    for (int p = 0; p < 2; p++) {
        const int i0 = iblk + 2*p, i1 = i0 + 1;

        // ---- geometry for both edges ----
        float rxa = s_xi[2*p][0]-xj0, rya = s_xi[2*p][1]-xj1, rza = s_xi[2*p][2]-xj2;
        float rxb = s_xi[2*p+1][0]-xj0, ryb = s_xi[2*p+1][1]-xj1, rzb = s_xi[2*p+1][2]-xj2;
        float d2a = rxa*rxa + rya*rya + rza*rza;
        float d2b = rxb*rxb + ryb*ryb + rzb*rzb;

        int ea = i0*(NP-1) + (j < i0 ? j : j-1); if (j == i0) ea = 0;
        int eb = i1*(NP-1) + (j < i1 ? j : j-1); if (j == i1) eb = 0;
        float dsa = d_static[b*NEDGE + ea];
        float dsb = d_static[b*NEDGE + eb];
        float ds2a = dsa*dsa, ds2b = dsb*dsb;

        u64 d2ap, ds2ap, d2bp, ds2bp;
        PACK2(d2ap, d2a, d2a);  PACK2(ds2ap, ds2a, ds2a);
        PACK2(d2bp, d2b, d2b);  PACK2(ds2bp, ds2b, ds2b);

        // ---- fused layer1 -> layer2 (HFMA2), both edges share weight loads ----
        __half2 ha[32], hb[32];
        {
            __half2 z = __float2half2_rn(0.0f);
#pragma unroll
            for (int f = 0; f < 32; f++) { ha[f] = z; hb[f] = z; }
        }
        {
            const u64* Ai0p = (const u64*)(s_misc + 192 + p*64);
            const u64* Ai1p = (const u64*)(s_misc + 224 + p*64);
            const u64* Wd   = (const u64*)(s_misc + 0);
            const u64* Wds  = (const u64*)(s_misc + 32);
#pragma unroll 4
            for (int kp = 0; kp < 16; kp++) {
                u64 bm = *(const u64*)(s_bm + j*SBM + 2*kp);
                u64 wd = Wd[kp], ws = Wds[kp];
                u64 pa, pb;
                ADD2(pa, Ai0p[kp], bm);
                FMA2(pa, d2ap, wd, pa);
                FMA2(pa, ds2ap, ws, pa);
                ADD2(pb, Ai1p[kp], bm);
                FMA2(pb, d2bp, wd, pb);
                FMA2(pb, ds2bp, ws, pb);
                float va0, va1, vb0, vb1;
                UNPK2(va0, va1, pa);
                UNPK2(vb0, vb1, pb);
                va0 = silut(va0); va1 = silut(va1);
                vb0 = silut(vb0); vb1 = silut(vb1);
                __half2 h2a = __floats2half2_rn(va0, va1);  // {s1[2kp], s1[2kp+1]}
                __half2 h2b = __floats2half2_rn(vb0, vb1);
                const uint4* wrow = (const uint4*)(s_w2h + kp*32);
#pragma unroll
                for (int q = 0; q < 8; q++) {
                    uint4 wv = wrow[q];
                    __half2 w0 = h2cast(wv.x), w1 = h2cast(wv.y);
                    __half2 w2 = h2cast(wv.z), w3 = h2cast(wv.w);
                    ha[4*q+0] = __hfma2(h2a, w0, ha[4*q+0]);
                    ha[4*q+1] = __hfma2(h2a, w1, ha[4*q+1]);
                    ha[4*q+2] = __hfma2(h2a, w2, ha[4*q+2]);
                    ha[4*q+3] = __hfma2(h2a, w3, ha[4*q+3]);
                    hb[4*q+0] = __hfma2(h2b, w0, hb[4*q+0]);
                    hb[4*q+1] = __hfma2(h2b, w1, hb[4*q+1]);
                    hb[4*q+2] = __hfma2(h2b, w2, hb[4*q+2]);
                    hb[4*q+3] = __hfma2(h2b, w3, hb[4*q+3]);
                }
            }
        }

        // ---- finalize (fp32): combine partials + bias + silu -> packed m ----
        u64 m2a[16], m2b[16];
#pragma unroll
        for (int q = 0; q < 16; q++) {
            float2 fa0 = __half22float2(ha[2*q]);
            float2 fa1 = __half22float2(ha[2*q+1]);
            float v0 = silut(fa0.x + fa0.y + s_misc[64 + 2*q]);
            float v1 = silut(fa1.x + fa1.y + s_misc[64 + 2*q + 1]);
            PACK2(m2a[q], v0, v1);
            float2 fb0 = __half22float2(hb[2*q]);
            float2 fb1 = __half22float2(hb[2*q+1]);
            v0 = silut(fb0.x + fb0.y + s_misc[64 + 2*q]);
            v1 = silut(fb1.x + fb1.y + s_misc[64 + 2*q + 1]);
            PACK2(m2b[q], v0, v1);
        }

        // ---- attention gates (packed fp32 dot) + validity mask folded in ----
        {
            const u64* awp = (const u64*)(s_misc + 128);
            u64 ata = 0ull, atb = 0ull;
#pragma unroll
            for (int q = 0; q < 16; q++) {
                u64 w = awp[q];
                FMA2(ata, m2a[q], w, ata);
                FMA2(atb, m2b[q], w, atb);
            }
            float a0, a1;
            UNPK2(a0, a1, ata);
            float atta = sigt(a0 + a1 + s_ab);
            UNPK2(a0, a1, atb);
            float attb = sigt(a0 + a1 + s_ab);
            if (j == i0) atta = 0.0f;      // mask diagonal edge a
            if (j == i1) attb = 0.0f;      // mask diagonal edge b
            u64 pa, pb;
            PACK2(pa, atta, atta);
            PACK2(pb, attb, attb);
#pragma unroll
            for (int q = 0; q < 16; q++) {
                MUL2(m2a[q], m2a[q], pa);
                MUL2(m2b[q], m2b[q], pb);
            }
        }

        // ---- spill masked m (edge a) to smem: frees m2a during coord head ----
#pragma unroll
        for (int q = 0; q < 16; q++)
            *(u64*)(s_red + j*SRD + 2*q) = m2a[q];
        __syncthreads();   // sync1: s_red(a) visible

        // ---- reduce-a: thread (f, q4) sums 32 j's of feature f ----
        {
            int f = t & 31, q4 = t >> 5;
            float acc = 0.0f;
            const float* base = s_red + (q4*32)*SRD + f;
#pragma unroll
            for (int n = 0; n < 32; n++) acc += base[n*SRD];
            s_part[0][q4][f] = acc;
        }

        // ---- coord head (HFMA2): interleaved edges, output-halved;
        //      edge-a m from smem, edge-b m from regs ----
        float acca = 0.0f, accb = 0.0f;
#pragma unroll
        for (int hc = 0; hc < 2; hc++) {
            __half2 ca[16], cbv[16];
            {
                __half2 z = __float2half2_rn(0.0f);
#pragma unroll
                for (int f = 0; f < 16; f++) { ca[f] = z; cbv[f] = z; }
            }
#pragma unroll 4
            for (int fp = 0; fp < 16; fp++) {
                u64 mav = *(const u64*)(s_red + j*SRD + 2*fp);
                float ma0, ma1, mb0, mb1;
                UNPK2(ma0, ma1, mav);
                UNPK2(mb0, mb1, m2b[fp]);
                __half2 h2a = __floats2half2_rn(ma0, ma1);   // {m[2fp], m[2fp+1]}
                __half2 h2b = __floats2half2_rn(mb0, mb1);
                const uint4* wrow = (const uint4*)(s_c1h + fp*32 + hc*16);
#pragma unroll
                for (int q = 0; q < 4; q++) {
                    uint4 wv = wrow[q];
                    __half2 w0 = h2cast(wv.x), w1 = h2cast(wv.y);
                    __half2 w2 = h2cast(wv.z), w3 = h2cast(wv.w);
                    ca[4*q+0] = __hfma2(h2a, w0, ca[4*q+0]);
                    ca[4*q+1] = __hfma2(h2a, w1, ca[4*q+1]);
                    ca[4*q+2] = __hfma2(h2a, w2, ca[4*q+2]);
                    ca[4*q+3] = __hfma2(h2a, w3, ca[4*q+3]);
                    cbv[4*q+0] = __hfma2(h2b, w0, cbv[4*q+0]);
                    cbv[4*q+1] = __hfma2(h2b, w1, cbv[4*q+1]);
                    cbv[4*q+2] = __hfma2(h2b, w2, cbv[4*q+2]);
                    cbv[4*q+3] = __hfma2(h2b, w3, cbv[4*q+3]);
                }
            }
#pragma unroll
            for (int f = 0; f < 16; f++) {
                float2 c = __half22float2(ca[f]);
                float cv = c.x + c.y + s_misc[96 + hc*16 + f];
                acca += silut(cv) * s_misc[160 + hc*16 + f];
                float2 cc = __half22float2(cbv[f]);
                cv = cc.x + cc.y + s_misc[96 + hc*16 + f];
                accb += silut(cv) * s_misc[160 + hc*16 + f];
            }
        }
        float transa = tanhap(acca);
        float transb = tanhap(accb);

        float valida = (j == i0) ? 0.0f : 1.0f;
        float validb = (j == i1) ? 0.0f : 1.0f;
        float da = sqrtf(d2a + 1e-6f);
        float db = sqrtf(d2b + 1e-6f);
        float coefa = valida * __fdividef(transa, da + 1.0f);
        float coefb = validb * __fdividef(transb, db + 1.0f);

        __syncthreads();   // sync2: all s_red(a) reads done

        // ---- spill masked m (edge b) and reduce-b ----
#pragma unroll
        for (int q = 0; q < 16; q++)
            *(u64*)(s_red + j*SRD + 2*q) = m2b[q];
        __syncthreads();   // sync3
        {
            int f = t & 31, q4 = t >> 5;
            float acc = 0.0f;
            const float* base = s_red + (q4*32)*SRD + f;
#pragma unroll
            for (int n = 0; n < 32; n++) acc += base[n*SRD];
            s_part[1][q4][f] = acc;
        }

        // ---- coord update reductions (both edges, warp butterfly) ----
        {
            float x0 = rxa*coefa, x1 = rya*coefa, x2 = rza*coefa;
            float y0 = rxb*coefb, y1 = ryb*coefb, y2 = rzb*coefb;
#pragma unroll
            for (int off = 16; off > 0; off >>= 1) {
                x0 += __shfl_xor_sync(0xffffffffu, x0, off);
                x1 += __shfl_xor_sync(0xffffffffu, x1, off);
                x2 += __shfl_xor_sync(0xffffffffu, x2, off);
                y0 += __shfl_xor_sync(0xffffffffu, y0, off);
                y1 += __shfl_xor_sync(0xffffffffu, y1, off);
                y2 += __shfl_xor_sync(0xffffffffu, y2, off);
            }
            if (lane == 0) {
                s_xp[0][warp][0] = x0; s_xp[0][warp][1] = x1; s_xp[0][warp][2] = x2;
                s_xp[1][warp][0] = y0; s_xp[1][warp][1] = y1; s_xp[1][warp][2] = y2;
            }
        }
        __syncthreads();   // sync4: s_part / s_xp ready

        // ---- tail: warp 0 -> node i0, warp 1 -> node i1 ----
        if (warp < 2) {
            int e = warp;
            int node = b*NP + i0 + e;
            int f = lane;
            if (f < 3) {
                float xs = s_xp[e][0][f] + s_xp[e][1][f] + s_xp[e][2][f] + s_xp[e][3][f];
                x_out[b*DIM + (i0+e)*ND + f] = s_xi[2*p+e][f] + xs * 5.0f;  // COORDS_RANGE
            }
            float mi = s_part[e][0][f] + s_part[e][1][f] + s_part[e][2][f] + s_part[e][3][f];
            float hv = h[node*FF + f];
            float acc = n_b1[f];
#pragma unroll
            for (int k = 0; k < FF; k++)
                acc += __shfl_sync(0xffffffffu, hv, k) * n_w1[k*HH + f];
#pragma unroll
            for (int k = 0; k < FF; k++)
                acc += __shfl_sync(0xffffffffu, mi, k) * n_w1[(FF + k)*HH + f];
            float tt2 = siluf(acc);
            float acc2 = n_b2[f];
#pragma unroll
            for (int k = 0; k < HH; k++)
                acc2 += __shfl_sync(0xffffffffu, tt2, k) * n_w2[k*FF + f];
            h_out[node*FF + f] = hv + acc2;
        }
    }
}

// ---------------------------------------------------------------------------
extern "C" void kernel_launch(void* const* d_in, const int* in_sizes, int n_in,
                              void* d_out, int out_size)
{
    const float* x        = (const float*)d_in[0];
    const float* h        = (const float*)d_in[1];
    const float* d_static = (const float*)d_in[2];
    const float* e_w1     = (const float*)d_in[3];
    const float* e_b1     = (const float*)d_in[4];
    const float* e_w2     = (const float*)d_in[5];
    const float* e_b2     = (const float*)d_in[6];
    const float* n_w1     = (const float*)d_in[7];
    const float* n_b1     = (const float*)d_in[8];
    const float* n_w2     = (const float*)d_in[9];
    const float* n_b2     = (const float*)d_in[10];
    const float* c_w1     = (const float*)d_in[11];
    const float* c_b1     = (const float*)d_in[12];
    const float* c_w2     = (const float*)d_in[13];
    const float* a_w      = (const float*)d_in[14];
    const float* a_b      = (const float*)d_in[15];

    float* out   = (float*)d_out;
    float* x_out = out;                 // B*DIM floats
    float* h_out = out + BB*DIM;        // B*NP*FF floats

    prenode_kernel<<<NNODE/4, 128>>>(h, e_w1, e_b1);
    edge_kernel<<<BB*NP/4, 128>>>(x, d_static, e_w1, e_w2, e_b2,
                                  c_w1, c_b1, c_w2, a_w, a_b,
                                  h, n_w1, n_b1, n_w2, n_b2,
                                  x_out, h_out);
}

// round 17
// speedup vs baseline: 3.5916x; 1.0374x over previous
#include <cuda_runtime.h>
#include <cuda_fp16.h>
#include <math.h>
#include <stdint.h>

#define NP 128
#define ND 3
#define DIM (NP*ND)
#define FF 32
#define HH 32
#define BB 128
#define NEDGE (NP*(NP-1))   // 16256
#define NNODE (BB*NP)       // 16384
#define SBM 34              // padded Bm row stride (floats)
#define SRH 17              // padded m-spill row stride (half2 units)

// scratch (static device arrays, no allocation)
__device__ float g_A [NNODE*FF];   // h_i @ W_hi + e_b1
__device__ float g_Bm[NNODE*FF];   // h_j @ W_hj

// ---- packed f32x2 helpers (FFMA2 via PTX) ----
#define FMA2(d,a,b,c) asm("fma.rn.f32x2 %0, %1, %2, %3;" : "=l"(d) : "l"(a), "l"(b), "l"(c))
#define ADD2(d,a,b)   asm("add.rn.f32x2 %0, %1, %2;"     : "=l"(d) : "l"(a), "l"(b))
#define MUL2(d,a,b)   asm("mul.rn.f32x2 %0, %1, %2;"     : "=l"(d) : "l"(a), "l"(b))
#define PACK2(d,lo,hi) asm("mov.b64 %0, {%1, %2};" : "=l"(d) : "f"(lo), "f"(hi))
#define UNPK2(lo,hi,s) asm("mov.b64 {%0, %1}, %2;" : "=f"(lo), "=f"(hi) : "l"(s))

typedef unsigned long long u64;

__device__ __forceinline__ float tanhap(float v) {
    float t;
    asm("tanh.approx.f32 %0, %1;" : "=f"(t) : "f"(v));
    return t;
}
// silu(v) = 0.5v * (1 + tanh(v/2))  -> 1 MUFU + 2 fma
__device__ __forceinline__ float silut(float v) {
    float hv = 0.5f * v;
    return fmaf(hv, tanhap(hv), hv);
}
// sigmoid(x) = 0.5 tanh(x/2) + 0.5
__device__ __forceinline__ float sigt(float v) {
    return fmaf(0.5f, tanhap(0.5f * v), 0.5f);
}
__device__ __forceinline__ float siluf(float v) {   // precise (node tail only)
    return __fdividef(v, 1.0f + __expf(-v));
}
__device__ __forceinline__ __half2 h2cast(unsigned int u) {
    return *reinterpret_cast<__half2*>(&u);
}
__device__ __forceinline__ unsigned int h2bits(__half2 h) {
    return *reinterpret_cast<unsigned int*>(&h);
}

// ---------------------------------------------------------------------------
// Kernel 0: per-node precompute A = h@W_hi + e_b1, Bm = h@W_hj
// ---------------------------------------------------------------------------
__global__ __launch_bounds__(128) void prenode_kernel(
    const float* __restrict__ h, const float* __restrict__ e_w1,
    const float* __restrict__ e_b1)
{
    int node = blockIdx.x * 4 + (threadIdx.x >> 5);
    int f    = threadIdx.x & 31;
    float hv = h[node*FF + f];
    float a  = e_b1[f];
    float bm = 0.0f;
#pragma unroll
    for (int k = 0; k < FF; k++) {
        float hk = __shfl_sync(0xffffffffu, hv, k);
        a  += hk * e_w1[k*HH + f];
        bm += hk * e_w1[(FF + k)*HH + f];
    }
    g_A [node*FF + f] = a;
    g_Bm[node*FF + f] = bm;
}

// ---------------------------------------------------------------------------
// Kernel 1: fused edge + node kernel.
// Block = (b, 4 i's = 2 pairs). Thread j handles edges (i0->j),(i1->j) per pair.
// GEMVs on HFMA2 with fp16 weights; m carried as half2 end-to-end (regs and
// smem spill/reduce), gate dot kept fp32 at finalize. Coord head streams
// edge-a m straight from half2 smem into HFMA2.
// ---------------------------------------------------------------------------
__global__ __launch_bounds__(128, 4) void edge_kernel(
    const float* __restrict__ x,      const float* __restrict__ d_static,
    const float* __restrict__ e_w1,   const float* __restrict__ e_w2,
    const float* __restrict__ e_b2,   const float* __restrict__ c_w1,
    const float* __restrict__ c_b1,   const float* __restrict__ c_w2,
    const float* __restrict__ a_w,    const float* __restrict__ a_b,
    const float* __restrict__ h,
    const float* __restrict__ n_w1,   const float* __restrict__ n_b1,
    const float* __restrict__ n_w2,   const float* __restrict__ n_b2,
    float* __restrict__ x_out,        float* __restrict__ h_out)
{
    // weight layout: s_w2h[kp*32 + f] = { W[2kp][f], W[2kp+1][f] }  (kp = k-pair)
    __shared__ __align__(16) __half2 s_w2h[16*32];   // e_w2, fp16 pairs (2KB)
    __shared__ __align__(16) __half2 s_c1h[16*32];   // c_w1, fp16 pairs (2KB)
    __shared__ __align__(16) float s_misc[10*32];    // wd,wds,eb2,cb1,aw,cw2,Ai0..Ai3
    __shared__ __align__(16) float s_bm[NP*SBM];     // staged Bm rows (batch b)
    __shared__ __align__(16) unsigned int s_redh[NP*SRH];  // m spill (half2), 8.5KB
    __shared__ float s_part[2][8][32];
    __shared__ float s_xp[2][4][3];
    __shared__ float s_xi[4][3];
    __shared__ float s_ab;

    const int t = threadIdx.x;
    const int b    = blockIdx.x >> 5;
    const int iblk = (blockIdx.x & 31) * 4;
    const int j = t;
    const int lane = t & 31;
    const int warp = t >> 5;

    // stage fp16 weight tiles (one-time)
    for (int idx = t; idx < 512; idx += 128) {
        int kp = idx >> 5, f = idx & 31;
        s_w2h[idx] = __floats2half2_rn(e_w2[(2*kp)*HH + f], e_w2[(2*kp+1)*HH + f]);
        s_c1h[idx] = __floats2half2_rn(c_w1[(2*kp)*HH + f], c_w1[(2*kp+1)*HH + f]);
    }
    {   // coalesced stage of Bm for batch b (128 rows x 32 floats), stride SBM
        const float4* src = (const float4*)(g_Bm + b*NP*FF);
#pragma unroll
        for (int q = 0; q < 8; q++) {
            int idx = q*128 + t;
            int row = idx >> 3;
            int col = (idx & 7) * 4;
            float4 v = src[idx];
            s_bm[row*SBM + col + 0] = v.x;
            s_bm[row*SBM + col + 1] = v.y;
            s_bm[row*SBM + col + 2] = v.z;
            s_bm[row*SBM + col + 3] = v.w;
        }
    }
    if (t < 32) {
        s_misc[t      ] = e_w1[(2*FF    )*HH + t];  // w_d
        s_misc[32 + t ] = e_w1[(2*FF + 1)*HH + t];  // w_ds
        s_misc[64 + t ] = e_b2[t];
        s_misc[96 + t ] = c_b1[t];
        s_misc[128 + t] = a_w[t];
        s_misc[160 + t] = c_w2[t];
    }
    // A_i rows for the 4 i's
    s_misc[192 + t] = g_A[(b*NP + iblk + (t >> 5))*FF + (t & 31)];
    if (t == 0) s_ab = a_b[0];
    if (t < 12) s_xi[t/3][t%3] = x[b*DIM + (iblk + t/3)*ND + (t%3)];
    __syncthreads();

    // invariant per-thread loads
    const float xj0 = x[b*DIM + j*ND + 0];
    const float xj1 = x[b*DIM + j*ND + 1];
    const float xj2 = x[b*DIM + j*ND + 2];

    for (int p = 0; p < 2; p++) {
        const int i0 = iblk + 2*p, i1 = i0 + 1;

        // ---- geometry for both edges ----
        float rxa = s_xi[2*p][0]-xj0, rya = s_xi[2*p][1]-xj1, rza = s_xi[2*p][2]-xj2;
        float rxb = s_xi[2*p+1][0]-xj0, ryb = s_xi[2*p+1][1]-xj1, rzb = s_xi[2*p+1][2]-xj2;
        float d2a = rxa*rxa + rya*rya + rza*rza;
        float d2b = rxb*rxb + ryb*ryb + rzb*rzb;

        int ea = i0*(NP-1) + (j < i0 ? j : j-1); if (j == i0) ea = 0;
        int eb = i1*(NP-1) + (j < i1 ? j : j-1); if (j == i1) eb = 0;
        float dsa = d_static[b*NEDGE + ea];
        float dsb = d_static[b*NEDGE + eb];
        float ds2a = dsa*dsa, ds2b = dsb*dsb;

        u64 d2ap, ds2ap, d2bp, ds2bp;
        PACK2(d2ap, d2a, d2a);  PACK2(ds2ap, ds2a, ds2a);
        PACK2(d2bp, d2b, d2b);  PACK2(ds2bp, ds2b, ds2b);

        // ---- fused layer1 -> layer2 (HFMA2), both edges share weight loads ----
        __half2 ha[32], hb[32];
        {
            __half2 z = __float2half2_rn(0.0f);
#pragma unroll
            for (int f = 0; f < 32; f++) { ha[f] = z; hb[f] = z; }
        }
        {
            const u64* Ai0p = (const u64*)(s_misc + 192 + p*64);
            const u64* Ai1p = (const u64*)(s_misc + 224 + p*64);
            const u64* Wd   = (const u64*)(s_misc + 0);
            const u64* Wds  = (const u64*)(s_misc + 32);
#pragma unroll 4
            for (int kp = 0; kp < 16; kp++) {
                u64 bm = *(const u64*)(s_bm + j*SBM + 2*kp);
                u64 wd = Wd[kp], ws = Wds[kp];
                u64 pa, pb;
                ADD2(pa, Ai0p[kp], bm);
                FMA2(pa, d2ap, wd, pa);
                FMA2(pa, ds2ap, ws, pa);
                ADD2(pb, Ai1p[kp], bm);
                FMA2(pb, d2bp, wd, pb);
                FMA2(pb, ds2bp, ws, pb);
                float va0, va1, vb0, vb1;
                UNPK2(va0, va1, pa);
                UNPK2(vb0, vb1, pb);
                va0 = silut(va0); va1 = silut(va1);
                vb0 = silut(vb0); vb1 = silut(vb1);
                __half2 h2a = __floats2half2_rn(va0, va1);  // {s1[2kp], s1[2kp+1]}
                __half2 h2b = __floats2half2_rn(vb0, vb1);
                const uint4* wrow = (const uint4*)(s_w2h + kp*32);
#pragma unroll
                for (int q = 0; q < 8; q++) {
                    uint4 wv = wrow[q];
                    __half2 w0 = h2cast(wv.x), w1 = h2cast(wv.y);
                    __half2 w2 = h2cast(wv.z), w3 = h2cast(wv.w);
                    ha[4*q+0] = __hfma2(h2a, w0, ha[4*q+0]);
                    ha[4*q+1] = __hfma2(h2a, w1, ha[4*q+1]);
                    ha[4*q+2] = __hfma2(h2a, w2, ha[4*q+2]);
                    ha[4*q+3] = __hfma2(h2a, w3, ha[4*q+3]);
                    hb[4*q+0] = __hfma2(h2b, w0, hb[4*q+0]);
                    hb[4*q+1] = __hfma2(h2b, w1, hb[4*q+1]);
                    hb[4*q+2] = __hfma2(h2b, w2, hb[4*q+2]);
                    hb[4*q+3] = __hfma2(h2b, w3, hb[4*q+3]);
                }
            }
        }

        // ---- finalize (fp32): combine + bias + silu; gate dot in fp32;
        //      m stored as half2[16] per edge ----
        __half2 mha[16], mhb[16];
        {
            u64 gta = 0ull, gtb = 0ull;
            const u64* awp = (const u64*)(s_misc + 128);
#pragma unroll
            for (int q = 0; q < 16; q++) {
                float2 fa0 = __half22float2(ha[2*q]);
                float2 fa1 = __half22float2(ha[2*q+1]);
                float v0 = silut(fa0.x + fa0.y + s_misc[64 + 2*q]);
                float v1 = silut(fa1.x + fa1.y + s_misc[64 + 2*q + 1]);
                u64 mv; PACK2(mv, v0, v1);
                FMA2(gta, mv, awp[q], gta);
                mha[q] = __floats2half2_rn(v0, v1);
                float2 fb0 = __half22float2(hb[2*q]);
                float2 fb1 = __half22float2(hb[2*q+1]);
                v0 = silut(fb0.x + fb0.y + s_misc[64 + 2*q]);
                v1 = silut(fb1.x + fb1.y + s_misc[64 + 2*q + 1]);
                PACK2(mv, v0, v1);
                FMA2(gtb, mv, awp[q], gtb);
                mhb[q] = __floats2half2_rn(v0, v1);
            }
            float a0, a1;
            UNPK2(a0, a1, gta);
            float atta = sigt(a0 + a1 + s_ab);
            UNPK2(a0, a1, gtb);
            float attb = sigt(a0 + a1 + s_ab);
            if (j == i0) atta = 0.0f;      // mask diagonal edge a
            if (j == i1) attb = 0.0f;      // mask diagonal edge b
            __half2 haat = __float2half2_rn(atta);
            __half2 hbat = __float2half2_rn(attb);
#pragma unroll
            for (int q = 0; q < 16; q++) {
                mha[q] = __hmul2(mha[q], haat);
                mhb[q] = __hmul2(mhb[q], hbat);
            }
        }

        // ---- spill masked m (edge a, half2) ----
#pragma unroll
        for (int q = 0; q < 16; q++)
            s_redh[j*SRH + q] = h2bits(mha[q]);
        __syncthreads();   // sync1: s_redh(a) visible

        // ---- reduce-a: thread (fp, grp) sums 16 rows of feature-pair fp ----
        {
            int fp = t & 15, grp = t >> 4;
            float r0 = 0.0f, r1 = 0.0f;
            const unsigned int* base = s_redh + (grp*16)*SRH + fp;
#pragma unroll
            for (int n = 0; n < 16; n++) {
                float2 f2 = __half22float2(h2cast(base[n*SRH]));
                r0 += f2.x; r1 += f2.y;
            }
            s_part[0][grp][2*fp]     = r0;
            s_part[0][grp][2*fp + 1] = r1;
        }

        // ---- coord head (HFMA2): edge-a m streamed from half2 smem,
        //      edge-b m from half2 regs; output-halved ----
        float acca = 0.0f, accb = 0.0f;
#pragma unroll
        for (int hc = 0; hc < 2; hc++) {
            __half2 ca[16], cbv[16];
            {
                __half2 z = __float2half2_rn(0.0f);
#pragma unroll
                for (int f = 0; f < 16; f++) { ca[f] = z; cbv[f] = z; }
            }
#pragma unroll 4
            for (int fp = 0; fp < 16; fp++) {
                __half2 h2a = h2cast(s_redh[j*SRH + fp]);   // {m[2fp], m[2fp+1]}
                __half2 h2b = mhb[fp];
                const uint4* wrow = (const uint4*)(s_c1h + fp*32 + hc*16);
#pragma unroll
                for (int q = 0; q < 4; q++) {
                    uint4 wv = wrow[q];
                    __half2 w0 = h2cast(wv.x), w1 = h2cast(wv.y);
                    __half2 w2 = h2cast(wv.z), w3 = h2cast(wv.w);
                    ca[4*q+0] = __hfma2(h2a, w0, ca[4*q+0]);
                    ca[4*q+1] = __hfma2(h2a, w1, ca[4*q+1]);
                    ca[4*q+2] = __hfma2(h2a, w2, ca[4*q+2]);
                    ca[4*q+3] = __hfma2(h2a, w3, ca[4*q+3]);
                    cbv[4*q+0] = __hfma2(h2b, w0, cbv[4*q+0]);
                    cbv[4*q+1] = __hfma2(h2b, w1, cbv[4*q+1]);
                    cbv[4*q+2] = __hfma2(h2b, w2, cbv[4*q+2]);
                    cbv[4*q+3] = __hfma2(h2b, w3, cbv[4*q+3]);
                }
            }
#pragma unroll
            for (int f = 0; f < 16; f++) {
                float2 c = __half22float2(ca[f]);
                float cv = c.x + c.y + s_misc[96 + hc*16 + f];
                acca += silut(cv) * s_misc[160 + hc*16 + f];
                float2 cc = __half22float2(cbv[f]);
                cv = cc.x + cc.y + s_misc[96 + hc*16 + f];
                accb += silut(cv) * s_misc[160 + hc*16 + f];
            }
        }
        float transa = tanhap(acca);
        float transb = tanhap(accb);

        float valida = (j == i0) ? 0.0f : 1.0f;
        float validb = (j == i1) ? 0.0f : 1.0f;
        float da = sqrtf(d2a + 1e-6f);
        float db = sqrtf(d2b + 1e-6f);
        float coefa = valida * __fdividef(transa, da + 1.0f);
        float coefb = validb * __fdividef(transb, db + 1.0f);

        __syncthreads();   // sync2: all s_redh(a) reads done

        // ---- spill masked m (edge b) and reduce-b ----
#pragma unroll
        for (int q = 0; q < 16; q++)
            s_redh[j*SRH + q] = h2bits(mhb[q]);
        __syncthreads();   // sync3
        {
            int fp = t & 15, grp = t >> 4;
            float r0 = 0.0f, r1 = 0.0f;
            const unsigned int* base = s_redh + (grp*16)*SRH + fp;
#pragma unroll
            for (int n = 0; n < 16; n++) {
                float2 f2 = __half22float2(h2cast(base[n*SRH]));
                r0 += f2.x; r1 += f2.y;
            }
            s_part[1][grp][2*fp]     = r0;
            s_part[1][grp][2*fp + 1] = r1;
        }

        // ---- coord update reductions (both edges, warp butterfly) ----
        {
            float x0 = rxa*coefa, x1 = rya*coefa, x2 = rza*coefa;
            float y0 = rxb*coefb, y1 = ryb*coefb, y2 = rzb*coefb;
#pragma unroll
            for (int off = 16; off > 0; off >>= 1) {
                x0 += __shfl_xor_sync(0xffffffffu, x0, off);
                x1 += __shfl_xor_sync(0xffffffffu, x1, off);
                x2 += __shfl_xor_sync(0xffffffffu, x2, off);
                y0 += __shfl_xor_sync(0xffffffffu, y0, off);
                y1 += __shfl_xor_sync(0xffffffffu, y1, off);
                y2 += __shfl_xor_sync(0xffffffffu, y2, off);
            }
            if (lane == 0) {
                s_xp[0][warp][0] = x0; s_xp[0][warp][1] = x1; s_xp[0][warp][2] = x2;
                s_xp[1][warp][0] = y0; s_xp[1][warp][1] = y1; s_xp[1][warp][2] = y2;
            }
        }
        __syncthreads();   // sync4: s_part / s_xp ready

        // ---- tail: warp 0 -> node i0, warp 1 -> node i1 ----
        if (warp < 2) {
            int e = warp;
            int node = b*NP + i0 + e;
            int f = lane;
            if (f < 3) {
                float xs = s_xp[e][0][f] + s_xp[e][1][f] + s_xp[e][2][f] + s_xp[e][3][f];
                x_out[b*DIM + (i0+e)*ND + f] = s_xi[2*p+e][f] + xs * 5.0f;  // COORDS_RANGE
            }
            float mi = 0.0f;
#pragma unroll
            for (int g = 0; g < 8; g++) mi += s_part[e][g][f];
            float hv = h[node*FF + f];
            float acc = n_b1[f];
#pragma unroll
            for (int k = 0; k < FF; k++)
                acc += __shfl_sync(0xffffffffu, hv, k) * n_w1[k*HH + f];
#pragma unroll
            for (int k = 0; k < FF; k++)
                acc += __shfl_sync(0xffffffffu, mi, k) * n_w1[(FF + k)*HH + f];
            float tt2 = siluf(acc);
            float acc2 = n_b2[f];
#pragma unroll
            for (int k = 0; k < HH; k++)
                acc2 += __shfl_sync(0xffffffffu, tt2, k) * n_w2[k*FF + f];
            h_out[node*FF + f] = hv + acc2;
        }
    }
}

// ---------------------------------------------------------------------------
extern "C" void kernel_launch(void* const* d_in, const int* in_sizes, int n_in,
                              void* d_out, int out_size)
{
    const float* x        = (const float*)d_in[0];
    const float* h        = (const float*)d_in[1];
    const float* d_static = (const float*)d_in[2];
    const float* e_w1     = (const float*)d_in[3];
    const float* e_b1     = (const float*)d_in[4];
    const float* e_w2     = (const float*)d_in[5];
    const float* e_b2     = (const float*)d_in[6];
    const float* n_w1     = (const float*)d_in[7];
    const float* n_b1     = (const float*)d_in[8];
    const float* n_w2     = (const float*)d_in[9];
    const float* n_b2     = (const float*)d_in[10];
    const float* c_w1     = (const float*)d_in[11];
    const float* c_b1     = (const float*)d_in[12];
    const float* c_w2     = (const float*)d_in[13];
    const float* a_w      = (const float*)d_in[14];
    const float* a_b      = (const float*)d_in[15];

    float* out   = (float*)d_out;
    float* x_out = out;                 // B*DIM floats
    float* h_out = out + BB*DIM;        // B*NP*FF floats

    prenode_kernel<<<NNODE/4, 128>>>(h, e_w1, e_b1);
    edge_kernel<<<BB*NP/4, 128>>>(x, d_static, e_w1, e_w2, e_b2,
                                  c_w1, c_b1, c_w2, a_w, a_b,
                                  h, n_w1, n_b1, n_w2, n_b2,
                                  x_out, h_out);
}